// round 1
// baseline (speedup 1.0000x reference)
#include <cuda_runtime.h>
#include <cuda_fp16.h>
#include <stdint.h>

#define M_DIM 2048
#define N_DIM 11008
#define K_DIM 4096

#define BM 128
#define BN 128
#define BK 32
#define LDA 40   // BK + 8 pad (halves)
#define LDB 40
#define KTILES (K_DIM / BK)

// fp16 copy of x (scratch: __device__ global per harness rules)
__device__ __half g_xh[(size_t)M_DIM * K_DIM];

// ---------------------------------------------------------------------------
// Kernel 0: x fp32 -> fp16
// ---------------------------------------------------------------------------
__global__ void convert_x_kernel(const float* __restrict__ x) {
    size_t i = ((size_t)blockIdx.x * blockDim.x + threadIdx.x) * 8;
    float4 f0 = *(const float4*)(x + i);
    float4 f1 = *(const float4*)(x + i + 4);
    __half2 h01 = __floats2half2_rn(f0.x, f0.y);
    __half2 h23 = __floats2half2_rn(f0.z, f0.w);
    __half2 h45 = __floats2half2_rn(f1.x, f1.y);
    __half2 h67 = __floats2half2_rn(f1.z, f1.w);
    uint4 v;
    v.x = *(uint32_t*)&h01; v.y = *(uint32_t*)&h23;
    v.z = *(uint32_t*)&h45; v.w = *(uint32_t*)&h67;
    *(uint4*)(g_xh + i) = v;
}

// ---------------------------------------------------------------------------
// Helpers
// ---------------------------------------------------------------------------
__device__ __forceinline__ uint32_t smem_u32(const void* p) {
    return (uint32_t)__cvta_generic_to_shared(p);
}

__device__ __forceinline__ void ldsm_x4(uint32_t& r0, uint32_t& r1,
                                        uint32_t& r2, uint32_t& r3,
                                        uint32_t addr) {
    asm volatile("ldmatrix.sync.aligned.m8n8.x4.shared.b16 {%0,%1,%2,%3}, [%4];"
                 : "=r"(r0), "=r"(r1), "=r"(r2), "=r"(r3)
                 : "r"(addr));
}

__device__ __forceinline__ void mma_16816(float c[4], const uint32_t a[4],
                                          const uint32_t b[2]) {
    asm volatile(
        "mma.sync.aligned.m16n8k16.row.col.f32.f16.f16.f32 "
        "{%0,%1,%2,%3}, {%4,%5,%6,%7}, {%8,%9}, {%0,%1,%2,%3};"
        : "+f"(c[0]), "+f"(c[1]), "+f"(c[2]), "+f"(c[3])
        : "r"(a[0]), "r"(a[1]), "r"(a[2]), "r"(a[3]), "r"(b[0]), "r"(b[1]));
}

// ---------------------------------------------------------------------------
// Kernel 1: quantized GEMM
//   out[m,n] = scale[n] * sum_k x[m,k] * (W_int[k,n] - zero[n]) + bias[n]
// ---------------------------------------------------------------------------
__global__ __launch_bounds__(256, 2)
void qgemm_kernel(const uint32_t* __restrict__ qw,
                  const float* __restrict__ scales,
                  const int* __restrict__ zeros,
                  const float* __restrict__ bias,
                  float* __restrict__ out) {
    __shared__ __half As[2][BM * LDA];
    __shared__ __half Bs[2][BN * LDB];

    const int tid = threadIdx.x;
    const int lane = tid & 31;
    const int wid = tid >> 5;
    const int warp_m = wid & 3;   // 0..3 -> 32-row slabs
    const int warp_n = wid >> 2;  // 0..1 -> 64-col slabs
    const int bm0 = blockIdx.y * BM;
    const int bn0 = blockIdx.x * BN;

    // ---- B fill mapping: thread owns fixed column n, half the k-groups ----
    const int n_loc = tid & 127;
    const int hh = tid >> 7;  // 0/1
    const int zq = zeros[bn0 + n_loc];
    const __half2 zc = __half2half2(__float2half_rn(1024.0f + (float)zq));
    const uint32_t* Bg = qw + (size_t)(bn0 + n_loc);

    // ---- A fill mapping: 512 16B chunks, 2 per thread ----
    const int rowA = tid >> 2;  // 0..63 (and +64)
    const int kqA = tid & 3;
    const __half* Ag = g_xh + (size_t)bm0 * K_DIM;

    float acc[2][8][4];
#pragma unroll
    for (int mi = 0; mi < 2; mi++)
#pragma unroll
        for (int ni = 0; ni < 8; ni++)
#pragma unroll
            for (int t = 0; t < 4; t++) acc[mi][ni][t] = 0.0f;

    uint4 a0r, a1r;
    uint32_t br[4];

    // ---- Prologue: load tile 0, fill smem buf 0 ----
    a0r = *(const uint4*)(Ag + (size_t)rowA * K_DIM + kqA * 8);
    a1r = *(const uint4*)(Ag + (size_t)(rowA + 64) * K_DIM + kqA * 8);
#pragma unroll
    for (int j = 0; j < 4; j++)
        br[j] = Bg[(size_t)(hh * 4 + j) * N_DIM];

    *(uint4*)(&As[0][rowA * LDA + kqA * 8]) = a0r;
    *(uint4*)(&As[0][(rowA + 64) * LDA + kqA * 8]) = a1r;
#pragma unroll
    for (int j = 0; j < 4; j++) {
        uint32_t w = br[j];
        uint32_t lo = __byte_perm(w, 0x64646464u, 0x4140);
        uint32_t hi = __byte_perm(w, 0x64646464u, 0x4342);
        __half2 h0 = __hsub2(*(__half2*)&lo, zc);
        __half2 h1 = __hsub2(*(__half2*)&hi, zc);
        uint2 st;
        st.x = *(uint32_t*)&h0;
        st.y = *(uint32_t*)&h1;
        *(uint2*)(&Bs[0][n_loc * LDB + (hh * 4 + j) * 4]) = st;
    }
    __syncthreads();

    int buf = 0;
#pragma unroll 1
    for (int kt = 0; kt < KTILES; kt++) {
        // Issue next tile's global loads early (latency overlap with MMA)
        if (kt + 1 < KTILES) {
            const int k0 = (kt + 1) * BK;
            a0r = *(const uint4*)(Ag + (size_t)rowA * K_DIM + k0 + kqA * 8);
            a1r = *(const uint4*)(Ag + (size_t)(rowA + 64) * K_DIM + k0 + kqA * 8);
#pragma unroll
            for (int j = 0; j < 4; j++)
                br[j] = Bg[(size_t)((kt + 1) * 8 + hh * 4 + j) * N_DIM];
        }

        // ---- Compute on current buffer ----
#pragma unroll
        for (int ks = 0; ks < 2; ks++) {
            const int g = lane >> 3, lr = lane & 7;
            uint32_t af[2][4];
#pragma unroll
            for (int mi = 0; mi < 2; mi++) {
                int row = warp_m * 32 + mi * 16 + (g & 1) * 8 + lr;
                int col = ks * 16 + (g >> 1) * 8;
                ldsm_x4(af[mi][0], af[mi][1], af[mi][2], af[mi][3],
                        smem_u32(&As[buf][row * LDA + col]));
            }
            uint32_t bf[8][2];
#pragma unroll
            for (int nj = 0; nj < 4; nj++) {
                int nrow = warp_n * 64 + nj * 16 + (g >> 1) * 8 + lr;
                int col = ks * 16 + (g & 1) * 8;
                uint32_t r0, r1, r2, r3;
                ldsm_x4(r0, r1, r2, r3, smem_u32(&Bs[buf][nrow * LDB + col]));
                bf[2 * nj][0] = r0;
                bf[2 * nj][1] = r1;
                bf[2 * nj + 1][0] = r2;
                bf[2 * nj + 1][1] = r3;
            }
#pragma unroll
            for (int mi = 0; mi < 2; mi++)
#pragma unroll
                for (int ni = 0; ni < 8; ni++)
                    mma_16816(acc[mi][ni], af[mi], bf[ni]);
        }

        // ---- Store staged regs into the other buffer ----
        if (kt + 1 < KTILES) {
            const int nb = buf ^ 1;
            *(uint4*)(&As[nb][rowA * LDA + kqA * 8]) = a0r;
            *(uint4*)(&As[nb][(rowA + 64) * LDA + kqA * 8]) = a1r;
#pragma unroll
            for (int j = 0; j < 4; j++) {
                uint32_t w = br[j];
                uint32_t lo = __byte_perm(w, 0x64646464u, 0x4140);
                uint32_t hi = __byte_perm(w, 0x64646464u, 0x4342);
                __half2 h0 = __hsub2(*(__half2*)&lo, zc);
                __half2 h1 = __hsub2(*(__half2*)&hi, zc);
                uint2 st;
                st.x = *(uint32_t*)&h0;
                st.y = *(uint32_t*)&h1;
                *(uint2*)(&Bs[nb][n_loc * LDB + (hh * 4 + j) * 4]) = st;
            }
            __syncthreads();
        }
        buf ^= 1;
    }

    // ---- Epilogue: out = acc * scale[n] + bias[n] ----
    const int m0 = bm0 + warp_m * 32;
    const int n0w = bn0 + warp_n * 64;
    const int lr = lane >> 2;        // 0..7
    const int lc = (lane & 3) * 2;   // 0,2,4,6
#pragma unroll
    for (int ni = 0; ni < 8; ni++) {
        const int col = n0w + ni * 8 + lc;
        const float s0 = scales[col], s1 = scales[col + 1];
        const float b0 = bias[col], b1 = bias[col + 1];
#pragma unroll
        for (int mi = 0; mi < 2; mi++) {
            const int r0 = m0 + mi * 16 + lr;
            float2 v0 = make_float2(acc[mi][ni][0] * s0 + b0,
                                    acc[mi][ni][1] * s1 + b1);
            *(float2*)(out + (size_t)r0 * N_DIM + col) = v0;
            float2 v1 = make_float2(acc[mi][ni][2] * s0 + b0,
                                    acc[mi][ni][3] * s1 + b1);
            *(float2*)(out + (size_t)(r0 + 8) * N_DIM + col) = v1;
        }
    }
}

// ---------------------------------------------------------------------------
// kernel_launch
// inputs (metadata order): x f32, qweight i32, scales f32, zeros i32, bias f32
// ---------------------------------------------------------------------------
extern "C" void kernel_launch(void* const* d_in, const int* in_sizes, int n_in,
                              void* d_out, int out_size) {
    const float* x = (const float*)d_in[0];
    const uint32_t* qw = (const uint32_t*)d_in[1];
    const float* scales = (const float*)d_in[2];
    const int* zeros = (const int*)d_in[3];
    const float* bias = (const float*)d_in[4];
    float* out = (float*)d_out;

    // x -> fp16: 2048*4096 elems, 8 per thread
    convert_x_kernel<<<(M_DIM * K_DIM) / (256 * 8), 256>>>(x);

    dim3 grid(N_DIM / BN, M_DIM / BM);  // 86 x 16
    qgemm_kernel<<<grid, 256>>>(qw, scales, zeros, bias, out);
}